// round 2
// baseline (speedup 1.0000x reference)
#include <cuda_runtime.h>
#include <cstdint>

// Problem dims
#define B_    256
#define T_    100
#define FIN   784
#define FHID  500
#define FOUT  10

// Neuron constants (f64 -> f32 rounded, matching JAX weak-type promotion)
#define EMF  0.7788007830714049f
#define A1F  1.1466802242428472f
#define A2F  -0.2865047968601901f

// Scratch (device globals; no allocation allowed)
__device__ float g_ann [25600000];   // [B,1000,T]  relu(W1 x + b1)
__device__ float g_psp2[12800000];   // [B,500,T]
__device__ float g_cur2[12800000];   // [B,500,T]
__device__ float g_psp3[12800000];   // [B,500,T]
__device__ float g_cur3[  256000];   // [B,10,T]

// ---------------------------------------------------------------------------
// Threefry2x32-20, key = (0, 42)  (jax.random.key(42))
// ---------------------------------------------------------------------------
__device__ __forceinline__ unsigned rotl32(unsigned x, int r) {
    return (x << r) | (x >> (32 - r));
}

__device__ __forceinline__ void threefry2x32_k42(unsigned c0, unsigned c1,
                                                 unsigned& o0, unsigned& o1) {
    const unsigned k0 = 0u, k1 = 42u;
    const unsigned k2 = 0x1BD11BDAu ^ k0 ^ k1;
    unsigned x0 = c0 + k0;
    unsigned x1 = c1 + k1;
#define TFR(r) { x0 += x1; x1 = rotl32(x1, (r)); x1 ^= x0; }
    TFR(13) TFR(15) TFR(26) TFR(6)
    x0 += k1; x1 += k2 + 1u;
    TFR(17) TFR(29) TFR(16) TFR(24)
    x0 += k2; x1 += k0 + 2u;
    TFR(13) TFR(15) TFR(26) TFR(6)
    x0 += k0; x1 += k1 + 3u;
    TFR(17) TFR(29) TFR(16) TFR(24)
    x0 += k1; x1 += k2 + 4u;
    TFR(13) TFR(15) TFR(26) TFR(6)
    x0 += k2; x1 += k0 + 5u;
#undef TFR
    o0 = x0; o1 = x1;
}

// ---------------------------------------------------------------------------
// XLA ErfInv32 (Giles approximation) — separate mul/add (no FMA contraction)
// ---------------------------------------------------------------------------
__device__ __forceinline__ float xla_erfinv32(float x) {
    float w = -log1pf(__fmul_rn(-x, x));
    float p;
    if (w < 5.0f) {
        w = __fadd_rn(w, -2.5f);
        p = 2.81022636e-08f;
        p = __fadd_rn(__fmul_rn(p, w),  3.43273939e-07f);
        p = __fadd_rn(__fmul_rn(p, w), -3.5233877e-06f);
        p = __fadd_rn(__fmul_rn(p, w), -4.39150654e-06f);
        p = __fadd_rn(__fmul_rn(p, w),  0.00021858087f);
        p = __fadd_rn(__fmul_rn(p, w), -0.00125372503f);
        p = __fadd_rn(__fmul_rn(p, w), -0.00417768164f);
        p = __fadd_rn(__fmul_rn(p, w),  0.246640727f);
        p = __fadd_rn(__fmul_rn(p, w),  1.50140941f);
    } else {
        w = __fadd_rn(sqrtf(w), -3.0f);
        p = -0.000200214257f;
        p = __fadd_rn(__fmul_rn(p, w),  0.000100950558f);
        p = __fadd_rn(__fmul_rn(p, w),  0.00134934322f);
        p = __fadd_rn(__fmul_rn(p, w), -0.00367342844f);
        p = __fadd_rn(__fmul_rn(p, w),  0.00573950773f);
        p = __fadd_rn(__fmul_rn(p, w), -0.0076224613f);
        p = __fadd_rn(__fmul_rn(p, w),  0.00943887047f);
        p = __fadd_rn(__fmul_rn(p, w),  1.00167406f);
        p = __fadd_rn(__fmul_rn(p, w),  2.83297682f);
    }
    return __fmul_rn(p, x);
}

// eps[i]: JAX partitionable threefry (default in modern JAX).
// Counter = 64-bit linear index -> (hi=0, lo=i); bits = out0 ^ out1.
__device__ __forceinline__ float jax_normal_eps(unsigned i) {
    unsigned r0, r1;
    threefry2x32_k42(0u, i, r0, r1);
    unsigned bits = r0 ^ r1;
    float f = __fadd_rn(__uint_as_float((bits >> 9) | 0x3f800000u), -1.0f); // [0,1)
    // u = max(lo, f*(hi-lo) + lo); hi-lo folds to exactly 2.0f, lo = nextafter(-1,0)
    float u = fmaxf(-0.99999994f,
                    __fadd_rn(__fmul_rn(f, 2.0f), -0.99999994f));
    return __fmul_rn(1.41421356237309515f, xla_erfinv32(u)); // sqrt(2)*erfinv
}

// ---------------------------------------------------------------------------
// SGEMM: Y[b,o,t] = sum_k W[o,k]*X[b,k,t] + bias[o]  (optional relu)
// n = b*T + t flattened; 64x64 tile, BK=16, 256 threads, 4x4 microtile.
// MODE 0: X = external (inputs), Y = g_ann ; MODE 1: X = g_psp2, Y = g_cur2
// ---------------------------------------------------------------------------
template<int O, int K, int RELU, int MODE>
__global__ __launch_bounds__(256)
void sgemm_bt(const float* __restrict__ W, const float* __restrict__ bias,
              const float* __restrict__ Xext) {
    const float* __restrict__ X = (MODE == 0) ? Xext : (const float*)g_psp2;
    float* __restrict__ Y       = (MODE == 0) ? g_ann : g_cur2;

    __shared__ float As[16][68];
    __shared__ float Bs[16][68];

    const int tid = threadIdx.x;
    const int tx  = tid & 15;
    const int ty  = tid >> 4;
    const int o0  = blockIdx.x * 64;
    const int n0  = blockIdx.y * 64;

    float acc[4][4] = {};

    const int a_o = tid >> 2;          // 0..63
    const int a_k = (tid & 3) * 4;     // 0,4,8,12
    const int b_n = tid & 63;          // 0..63
    const int b_k = tid >> 6;          // 0..3

    const int n_g = n0 + b_n;
    const int bb  = n_g / T_;
    const int tt  = n_g - bb * T_;
    const float* Xcol = X + bb * (K * T_) + tt;

    const int o_a = o0 + a_o;
    const bool o_ok = (o_a < O);

    for (int k0 = 0; k0 < K; k0 += 16) {
        {
            float4 v = make_float4(0.f, 0.f, 0.f, 0.f);
            int k = k0 + a_k;
            if (o_ok) {
                if (k + 3 < K) {
                    v = *reinterpret_cast<const float4*>(W + o_a * K + k);
                } else {
                    float e0 = (k + 0 < K) ? W[o_a * K + k + 0] : 0.f;
                    float e1 = (k + 1 < K) ? W[o_a * K + k + 1] : 0.f;
                    float e2 = (k + 2 < K) ? W[o_a * K + k + 2] : 0.f;
                    float e3 = (k + 3 < K) ? W[o_a * K + k + 3] : 0.f;
                    v = make_float4(e0, e1, e2, e3);
                }
            }
            As[a_k + 0][a_o] = v.x;
            As[a_k + 1][a_o] = v.y;
            As[a_k + 2][a_o] = v.z;
            As[a_k + 3][a_o] = v.w;
        }
        #pragma unroll
        for (int j = 0; j < 4; j++) {
            int kr = b_k + j * 4;
            int k  = k0 + kr;
            Bs[kr][b_n] = (k < K) ? Xcol[k * T_] : 0.f;
        }
        __syncthreads();

        #pragma unroll
        for (int kk = 0; kk < 16; kk++) {
            float4 a = *reinterpret_cast<const float4*>(&As[kk][ty * 4]);
            float4 b = *reinterpret_cast<const float4*>(&Bs[kk][tx * 4]);
            acc[0][0] += a.x * b.x; acc[0][1] += a.x * b.y; acc[0][2] += a.x * b.z; acc[0][3] += a.x * b.w;
            acc[1][0] += a.y * b.x; acc[1][1] += a.y * b.y; acc[1][2] += a.y * b.z; acc[1][3] += a.y * b.w;
            acc[2][0] += a.z * b.x; acc[2][1] += a.z * b.y; acc[2][2] += a.z * b.z; acc[2][3] += a.z * b.w;
            acc[3][0] += a.w * b.x; acc[3][1] += a.w * b.y; acc[3][2] += a.w * b.z; acc[3][3] += a.w * b.w;
        }
        __syncthreads();
    }

    #pragma unroll
    for (int i = 0; i < 4; i++) {
        int o = o0 + ty * 4 + i;
        if (o >= O) continue;
        float bv = bias[o];
        #pragma unroll
        for (int j = 0; j < 4; j++) {
            int n = n0 + tx * 4 + j;
            int b = n / T_;
            int t = n - b * T_;
            float v = __fadd_rn(acc[i][j], bv);
            if (RELU) v = fmaxf(v, 0.0f);
            Y[b * (O * T_) + o * T_ + t] = v;
        }
    }
}

// ---------------------------------------------------------------------------
// coding = mu + eps * exp(0.5*ln_var) ; psp2 = dual-exp IIR of coding
// ---------------------------------------------------------------------------
__global__ __launch_bounds__(256)
void coding_psp2_kernel() {
    int idx = blockIdx.x * blockDim.x + threadIdx.x;
    if (idx >= B_ * FHID) return;
    int b = idx / FHID;
    int f = idx - b * FHID;
    const float* mu = g_ann + b * 100000 + f * T_;
    const float* lv = g_ann + b * 100000 + (FHID + f) * T_;
    float* out = g_psp2 + idx * T_;
    unsigned base = (unsigned)idx * 100u;
    float y1 = 0.f, y2 = 0.f;
    #pragma unroll 4
    for (int t = 0; t < T_; t++) {
        float eps = jax_normal_eps(base + (unsigned)t);
        float sc  = expf(__fmul_rn(0.5f, lv[t]));
        float cod = __fadd_rn(mu[t], __fmul_rn(eps, sc));
        float y   = __fadd_rn(__fadd_rn(__fmul_rn(A1F, y1), __fmul_rn(A2F, y2)), cod);
        out[t] = y;
        y2 = y1; y1 = y;
    }
}

// ---------------------------------------------------------------------------
// LIF (layer 2) fused with dual-exp IIR producing psp3 directly
// ---------------------------------------------------------------------------
__global__ __launch_bounds__(256)
void lif2_psp3_kernel() {
    int idx = blockIdx.x * blockDim.x + threadIdx.x;
    if (idx >= B_ * FHID) return;
    const float* c = g_cur2 + idx * T_;
    float* out = g_psp3 + idx * T_;
    float v = 0.f, s = 0.f, y1 = 0.f, y2 = 0.f;
    #pragma unroll 4
    for (int t = 0; t < T_; t++) {
        float vn = __fadd_rn(__fmul_rn(__fmul_rn(v, EMF), __fsub_rn(1.0f, s)), c[t]);
        float spk = (vn > 1.0f) ? 1.0f : 0.0f;
        v = vn; s = spk;
        float y = __fadd_rn(__fadd_rn(__fmul_rn(A1F, y1), __fmul_rn(A2F, y2)), spk);
        out[t] = y;
        y2 = y1; y1 = y;
    }
}

// ---------------------------------------------------------------------------
// GEMM3: cur3[b,o,t] = sum_k W3[o,k]*psp3[b,k,t] + b3[o]   (O=10, K=500)
// ---------------------------------------------------------------------------
__global__ __launch_bounds__(1024)
void gemm3_kernel(const float* __restrict__ W3, const float* __restrict__ b3) {
    __shared__ float Ws[FOUT * FHID];   // 20 KB
    int b = blockIdx.x;
    for (int i = threadIdx.x; i < FOUT * FHID; i += blockDim.x) Ws[i] = W3[i];
    __syncthreads();
    int tid = threadIdx.x;
    if (tid < FOUT * T_) {
        int o = tid / T_;
        int t = tid - o * T_;
        const float* p = g_psp3 + b * (FHID * T_) + t;
        const float* w = Ws + o * FHID;
        float acc = 0.f;
        #pragma unroll 10
        for (int k = 0; k < FHID; k++) acc += w[k] * p[k * T_];
        g_cur3[b * 1000 + tid] = __fadd_rn(acc, b3[o]);
    }
}

// ---------------------------------------------------------------------------
// LIF (layer 3) -> output spikes
// ---------------------------------------------------------------------------
__global__ __launch_bounds__(256)
void lif3_kernel(float* __restrict__ out) {
    int idx = blockIdx.x * blockDim.x + threadIdx.x;
    if (idx >= B_ * FOUT) return;
    const float* c = g_cur3 + idx * T_;
    float* op = out + idx * T_;
    float v = 0.f, s = 0.f;
    #pragma unroll 4
    for (int t = 0; t < T_; t++) {
        float vn = __fadd_rn(__fmul_rn(__fmul_rn(v, EMF), __fsub_rn(1.0f, s)), c[t]);
        float spk = (vn > 1.0f) ? 1.0f : 0.0f;
        v = vn; s = spk;
        op[t] = spk;
    }
}

// ---------------------------------------------------------------------------
extern "C" void kernel_launch(void* const* d_in, const int* in_sizes, int n_in,
                              void* d_out, int out_size) {
    const float* inputs = (const float*)d_in[0];  // [256,784,100]
    const float* W1     = (const float*)d_in[1];  // [1000,784]
    const float* b1     = (const float*)d_in[2];  // [1000]
    const float* W2     = (const float*)d_in[3];  // [500,500]
    const float* b2     = (const float*)d_in[4];  // [500]
    const float* W3     = (const float*)d_in[5];  // [10,500]
    const float* b3     = (const float*)d_in[6];  // [10]
    float* out          = (float*)d_out;          // [256,10,100]

    {
        dim3 grid((1000 + 63) / 64, (B_ * T_) / 64);   // 16 x 400
        sgemm_bt<1000, FIN, 1, 0><<<grid, 256>>>(W1, b1, inputs);
    }
    coding_psp2_kernel<<<(B_ * FHID + 255) / 256, 256>>>();
    {
        dim3 grid((FHID + 63) / 64, (B_ * T_) / 64);   // 8 x 400
        sgemm_bt<FHID, FHID, 0, 1><<<grid, 256>>>(W2, b2, nullptr);
    }
    lif2_psp3_kernel<<<(B_ * FHID + 255) / 256, 256>>>();
    gemm3_kernel<<<B_, 1024>>>(W3, b3);
    lif3_kernel<<<(B_ * FOUT + 255) / 256, 256>>>(out);
}

// round 3
// speedup vs baseline: 1.2868x; 1.2868x over previous
#include <cuda_runtime.h>
#include <cstdint>

// Problem dims
#define B_    256
#define T_    100
#define FIN   784
#define FHID  500
#define FOUT  10
#define NTOK  25600   // B_*T_

// Neuron constants (f64 -> f32 rounded, matching JAX weak-type promotion)
#define EMF  0.7788007830714049f
#define A1F  1.1466802242428472f
#define A2F  -0.2865047968601901f

// Scratch (device globals; no allocation allowed). Token-major layout [n, F].
__device__ float g_ann [NTOK * 1000];  // [n, 1000] relu(W1 x + b1)
__device__ float g_psp2[NTOK * FHID];  // [n, 500]
__device__ float g_cur2[NTOK * FHID];  // [n, 500]
__device__ float g_psp3[NTOK * FHID];  // [n, 500]
__device__ float g_cur3[NTOK * FOUT];  // [n, 10]

// ---------------------------------------------------------------------------
// Threefry2x32-20, key = (0, 42)
// ---------------------------------------------------------------------------
__device__ __forceinline__ unsigned rotl32(unsigned x, int r) {
    return (x << r) | (x >> (32 - r));
}

__device__ __forceinline__ void threefry2x32_k42(unsigned c0, unsigned c1,
                                                 unsigned& o0, unsigned& o1) {
    const unsigned k0 = 0u, k1 = 42u;
    const unsigned k2 = 0x1BD11BDAu ^ k0 ^ k1;
    unsigned x0 = c0 + k0;
    unsigned x1 = c1 + k1;
#define TFR(r) { x0 += x1; x1 = rotl32(x1, (r)); x1 ^= x0; }
    TFR(13) TFR(15) TFR(26) TFR(6)
    x0 += k1; x1 += k2 + 1u;
    TFR(17) TFR(29) TFR(16) TFR(24)
    x0 += k2; x1 += k0 + 2u;
    TFR(13) TFR(15) TFR(26) TFR(6)
    x0 += k0; x1 += k1 + 3u;
    TFR(17) TFR(29) TFR(16) TFR(24)
    x0 += k1; x1 += k2 + 4u;
    TFR(13) TFR(15) TFR(26) TFR(6)
    x0 += k2; x1 += k0 + 5u;
#undef TFR
    o0 = x0; o1 = x1;
}

// XLA ErfInv32 (Giles) — separate mul/add, no FMA contraction
__device__ __forceinline__ float xla_erfinv32(float x) {
    float w = -log1pf(__fmul_rn(-x, x));
    float p;
    if (w < 5.0f) {
        w = __fadd_rn(w, -2.5f);
        p = 2.81022636e-08f;
        p = __fadd_rn(__fmul_rn(p, w),  3.43273939e-07f);
        p = __fadd_rn(__fmul_rn(p, w), -3.5233877e-06f);
        p = __fadd_rn(__fmul_rn(p, w), -4.39150654e-06f);
        p = __fadd_rn(__fmul_rn(p, w),  0.00021858087f);
        p = __fadd_rn(__fmul_rn(p, w), -0.00125372503f);
        p = __fadd_rn(__fmul_rn(p, w), -0.00417768164f);
        p = __fadd_rn(__fmul_rn(p, w),  0.246640727f);
        p = __fadd_rn(__fmul_rn(p, w),  1.50140941f);
    } else {
        w = __fadd_rn(sqrtf(w), -3.0f);
        p = -0.000200214257f;
        p = __fadd_rn(__fmul_rn(p, w),  0.000100950558f);
        p = __fadd_rn(__fmul_rn(p, w),  0.00134934322f);
        p = __fadd_rn(__fmul_rn(p, w), -0.00367342844f);
        p = __fadd_rn(__fmul_rn(p, w),  0.00573950773f);
        p = __fadd_rn(__fmul_rn(p, w), -0.0076224613f);
        p = __fadd_rn(__fmul_rn(p, w),  0.00943887047f);
        p = __fadd_rn(__fmul_rn(p, w),  1.00167406f);
        p = __fadd_rn(__fmul_rn(p, w),  2.83297682f);
    }
    return __fmul_rn(p, x);
}

// eps[i]: JAX partitionable threefry. counter=(0,i); bits = out0 ^ out1.
__device__ __forceinline__ float jax_normal_eps(unsigned i) {
    unsigned r0, r1;
    threefry2x32_k42(0u, i, r0, r1);
    unsigned bits = r0 ^ r1;
    float f = __fadd_rn(__uint_as_float((bits >> 9) | 0x3f800000u), -1.0f);
    float u = fmaxf(-0.99999994f,
                    __fadd_rn(__fmul_rn(f, 2.0f), -0.99999994f));
    return __fmul_rn(1.41421356237309515f, xla_erfinv32(u));
}

// ---------------------------------------------------------------------------
// SGEMM 128x128, BK=8, 256 threads, 8x8 microtile, double-buffered.
// Y[n*O + o] = sum_k W[o,k] * X[k, n] + bias[o]   (optional relu)
// MODE 0: X = inputs [b,784,t] (strided), Y = g_ann
// MODE 1: X = g_psp2 row-major [n, K],    Y = g_cur2
// ---------------------------------------------------------------------------
template<int O, int K, int MODE, int RELU>
__global__ __launch_bounds__(256, 2)
void sgemm128(const float* __restrict__ W, const float* __restrict__ bias,
              const float* __restrict__ Xext) {
    const float* __restrict__ X = (MODE == 0) ? Xext : (const float*)g_psp2;
    float* __restrict__ Y       = (MODE == 0) ? g_ann : g_cur2;

    __shared__ __align__(16) float As[2][8][132];
    __shared__ __align__(16) float Bs[2][8][132];

    const int tid = threadIdx.x;
    const int o0  = blockIdx.x * 128;
    const int n0  = blockIdx.y * 128;
    const int tr  = tid >> 4;   // 0..15
    const int tc  = tid & 15;   // 0..15

    // A loader: row = tid>>1 (0..127), k4 = (tid&1)*4
    const int a_row = tid >> 1;
    const int a_k   = (tid & 1) * 4;
    const int o_a   = o0 + a_row;
    const bool a_ok = (o_a < O);
    const float* Wp = W + (a_ok ? o_a : 0) * K;

    // B loader
    int bm_k = 0, bm_n = 0;          // MODE 0
    int baseB[4] = {0, 0, 0, 0};
    const float* Bp = nullptr;       // MODE 1
    int b_row = 0, b_k4 = 0;
    if (MODE == 0) {
        bm_k = tid >> 5;             // 0..7
        bm_n = tid & 31;             // 0..31
        #pragma unroll
        for (int j = 0; j < 4; j++) {
            int n_g = n0 + bm_n + 32 * j;
            int bb  = n_g / T_;
            int tt  = n_g - bb * T_;
            baseB[j] = bb * (FIN * T_) + tt;
        }
    } else {
        b_row = tid >> 1;
        b_k4  = (tid & 1) * 4;
        Bp = X + (n0 + b_row) * K;
    }

    float4 aR;
    float  bR[4];

    auto loadA = [&](int k0) {
        float4 v = make_float4(0.f, 0.f, 0.f, 0.f);
        if (a_ok) {
            int kb = k0 + a_k;
            if ((K % 8 == 0) || (kb + 3 < K)) {
                v = *reinterpret_cast<const float4*>(Wp + kb);
            } else {
                if (kb + 0 < K) v.x = Wp[kb + 0];
                if (kb + 1 < K) v.y = Wp[kb + 1];
                if (kb + 2 < K) v.z = Wp[kb + 2];
                if (kb + 3 < K) v.w = Wp[kb + 3];
            }
        }
        aR = v;
    };

    auto loadB = [&](int k0) {
        if (MODE == 0) {
            int kb = k0 + bm_k;
            bool ok = (K % 8 == 0) || (kb < K);
            #pragma unroll
            for (int j = 0; j < 4; j++)
                bR[j] = ok ? X[baseB[j] + kb * T_] : 0.f;
        } else {
            float4 v = make_float4(0.f, 0.f, 0.f, 0.f);
            int kb = k0 + b_k4;
            if ((K % 8 == 0) || (kb + 3 < K)) {
                v = *reinterpret_cast<const float4*>(Bp + kb);
            } else {
                if (kb + 0 < K) v.x = Bp[kb + 0];
                if (kb + 1 < K) v.y = Bp[kb + 1];
                if (kb + 2 < K) v.z = Bp[kb + 2];
                if (kb + 3 < K) v.w = Bp[kb + 3];
            }
            bR[0] = v.x; bR[1] = v.y; bR[2] = v.z; bR[3] = v.w;
        }
    };

    auto storeTiles = [&](int buf) {
        As[buf][a_k + 0][a_row] = aR.x;
        As[buf][a_k + 1][a_row] = aR.y;
        As[buf][a_k + 2][a_row] = aR.z;
        As[buf][a_k + 3][a_row] = aR.w;
        if (MODE == 0) {
            #pragma unroll
            for (int j = 0; j < 4; j++) Bs[buf][bm_k][bm_n + 32 * j] = bR[j];
        } else {
            #pragma unroll
            for (int i = 0; i < 4; i++) Bs[buf][b_k4 + i][b_row] = bR[i];
        }
    };

    float acc[8][8];
    #pragma unroll
    for (int i = 0; i < 8; i++)
        #pragma unroll
        for (int j = 0; j < 8; j++) acc[i][j] = 0.f;

    constexpr int NT = (K + 7) / 8;
    loadA(0); loadB(0); storeTiles(0);
    __syncthreads();

    for (int kt = 0; kt < NT; kt++) {
        const int buf = kt & 1;
        if (kt + 1 < NT) { loadA((kt + 1) * 8); loadB((kt + 1) * 8); }
        #pragma unroll
        for (int kk = 0; kk < 8; kk++) {
            float4 a0 = *reinterpret_cast<const float4*>(&As[buf][kk][tr * 4]);
            float4 a1 = *reinterpret_cast<const float4*>(&As[buf][kk][tr * 4 + 64]);
            float4 b0 = *reinterpret_cast<const float4*>(&Bs[buf][kk][tc * 4]);
            float4 b1 = *reinterpret_cast<const float4*>(&Bs[buf][kk][tc * 4 + 64]);
            float av[8] = {a0.x, a0.y, a0.z, a0.w, a1.x, a1.y, a1.z, a1.w};
            float bv[8] = {b0.x, b0.y, b0.z, b0.w, b1.x, b1.y, b1.z, b1.w};
            #pragma unroll
            for (int i = 0; i < 8; i++)
                #pragma unroll
                for (int j = 0; j < 8; j++)
                    acc[i][j] += av[i] * bv[j];
        }
        if (kt + 1 < NT) storeTiles(buf ^ 1);
        __syncthreads();
    }

    // Epilogue: write Y[n*O + o], float4 along o.
    #pragma unroll
    for (int g = 0; g < 2; g++) {
        const int o = o0 + tr * 4 + g * 64;
        if (o >= O) continue;   // O%4==0, o%4==0 -> whole float4 valid
        float4 bv4 = *reinterpret_cast<const float4*>(&bias[o]);
        #pragma unroll
        for (int j = 0; j < 8; j++) {
            const int n = n0 + tc * 4 + ((j < 4) ? j : j + 60);
            float4 v;
            v.x = __fadd_rn(acc[4 * g + 0][j], bv4.x);
            v.y = __fadd_rn(acc[4 * g + 1][j], bv4.y);
            v.z = __fadd_rn(acc[4 * g + 2][j], bv4.z);
            v.w = __fadd_rn(acc[4 * g + 3][j], bv4.w);
            if (RELU) {
                v.x = fmaxf(v.x, 0.f); v.y = fmaxf(v.y, 0.f);
                v.z = fmaxf(v.z, 0.f); v.w = fmaxf(v.w, 0.f);
            }
            *reinterpret_cast<float4*>(&Y[n * O + o]) = v;
        }
    }
}

// ---------------------------------------------------------------------------
// coding = mu + eps * exp(0.5*ln_var) ; psp2 = dual-exp IIR (coalesced layout)
// ---------------------------------------------------------------------------
__global__ __launch_bounds__(256)
void coding_psp2_kernel() {
    int idx = blockIdx.x * blockDim.x + threadIdx.x;   // b*500+f
    if (idx >= B_ * FHID) return;
    int b = idx / FHID;
    int f = idx - b * FHID;
    const float* mu = g_ann + b * (T_ * 1000) + f;      // stride 1000 per t
    const float* lv = mu + FHID;
    float* out = g_psp2 + b * (T_ * FHID) + f;          // stride 500 per t
    unsigned base = (unsigned)idx * 100u;
    float y1 = 0.f, y2 = 0.f;
    #pragma unroll 4
    for (int t = 0; t < T_; t++) {
        float eps = jax_normal_eps(base + (unsigned)t);
        float sc  = expf(__fmul_rn(0.5f, lv[t * 1000]));
        float cod = __fadd_rn(mu[t * 1000], __fmul_rn(eps, sc));
        float y   = __fadd_rn(__fadd_rn(__fmul_rn(A1F, y1), __fmul_rn(A2F, y2)), cod);
        out[t * FHID] = y;
        y2 = y1; y1 = y;
    }
}

// ---------------------------------------------------------------------------
// LIF (layer 2) fused with dual-exp IIR -> psp3 (coalesced layout)
// ---------------------------------------------------------------------------
__global__ __launch_bounds__(256)
void lif2_psp3_kernel() {
    int idx = blockIdx.x * blockDim.x + threadIdx.x;   // b*500+f
    if (idx >= B_ * FHID) return;
    int b = idx / FHID;
    int f = idx - b * FHID;
    const float* c = g_cur2 + b * (T_ * FHID) + f;
    float* out     = g_psp3 + b * (T_ * FHID) + f;
    float v = 0.f, s = 0.f, y1 = 0.f, y2 = 0.f;
    #pragma unroll 4
    for (int t = 0; t < T_; t++) {
        float vn = __fadd_rn(__fmul_rn(__fmul_rn(v, EMF), __fsub_rn(1.0f, s)), c[t * FHID]);
        float spk = (vn > 1.0f) ? 1.0f : 0.0f;
        v = vn; s = spk;
        float y = __fadd_rn(__fadd_rn(__fmul_rn(A1F, y1), __fmul_rn(A2F, y2)), spk);
        out[t * FHID] = y;
        y2 = y1; y1 = y;
    }
}

// ---------------------------------------------------------------------------
// GEMM3: cur3[n,o] = sum_k W3[o,k]*psp3[n,k] + b3[o]   (O=10, K=500)
// ---------------------------------------------------------------------------
__global__ __launch_bounds__(256)
void gemm3_kernel(const float* __restrict__ W3, const float* __restrict__ b3) {
    __shared__ __align__(16) float Ws[FOUT * FHID];   // 20 KB
    for (int i = threadIdx.x; i < FOUT * FHID; i += 256) Ws[i] = W3[i];
    __syncthreads();
    int n = blockIdx.x * 256 + threadIdx.x;           // < 25600
    float acc[FOUT];
    #pragma unroll
    for (int o = 0; o < FOUT; o++) acc[o] = 0.f;
    const float4* xp = reinterpret_cast<const float4*>(g_psp3 + n * FHID);
    #pragma unroll 5
    for (int k4 = 0; k4 < FHID / 4; k4++) {
        float4 x = xp[k4];
        #pragma unroll
        for (int o = 0; o < FOUT; o++) {
            float4 w = *reinterpret_cast<const float4*>(&Ws[o * FHID + k4 * 4]);
            acc[o] += w.x * x.x;
            acc[o] += w.y * x.y;
            acc[o] += w.z * x.z;
            acc[o] += w.w * x.w;
        }
    }
    #pragma unroll
    for (int o = 0; o < FOUT; o++)
        g_cur3[n * FOUT + o] = __fadd_rn(acc[o], b3[o]);
}

// ---------------------------------------------------------------------------
// LIF (layer 3) -> output spikes [b,o,t]
// ---------------------------------------------------------------------------
__global__ __launch_bounds__(256)
void lif3_kernel(float* __restrict__ out) {
    int idx = blockIdx.x * blockDim.x + threadIdx.x;   // b*10+o
    if (idx >= B_ * FOUT) return;
    int b = idx / FOUT;
    int o = idx - b * FOUT;
    const float* c = g_cur3 + b * (T_ * FOUT) + o;     // stride 10 per t
    float* op = out + idx * T_;
    float v = 0.f, s = 0.f;
    #pragma unroll 4
    for (int t = 0; t < T_; t++) {
        float vn = __fadd_rn(__fmul_rn(__fmul_rn(v, EMF), __fsub_rn(1.0f, s)), c[t * FOUT]);
        float spk = (vn > 1.0f) ? 1.0f : 0.0f;
        v = vn; s = spk;
        op[t] = spk;
    }
}

// ---------------------------------------------------------------------------
extern "C" void kernel_launch(void* const* d_in, const int* in_sizes, int n_in,
                              void* d_out, int out_size) {
    const float* inputs = (const float*)d_in[0];  // [256,784,100]
    const float* W1     = (const float*)d_in[1];  // [1000,784]
    const float* b1     = (const float*)d_in[2];  // [1000]
    const float* W2     = (const float*)d_in[3];  // [500,500]
    const float* b2     = (const float*)d_in[4];  // [500]
    const float* W3     = (const float*)d_in[5];  // [10,500]
    const float* b3     = (const float*)d_in[6];  // [10]
    float* out          = (float*)d_out;          // [256,10,100]

    // Layer 1: ann = relu(W1 @ x + b1) -> g_ann [n, 1000]
    sgemm128<1000, FIN, 0, 1><<<dim3(8, 200), 256>>>(W1, b1, inputs);
    // coding + IIR -> g_psp2 [n, 500]
    coding_psp2_kernel<<<(B_ * FHID + 255) / 256, 256>>>();
    // Layer 2 GEMM -> g_cur2 [n, 500]
    sgemm128<FHID, FHID, 1, 0><<<dim3(4, 200), 256>>>(W2, b2, nullptr);
    // LIF2 + IIR -> g_psp3 [n, 500]
    lif2_psp3_kernel<<<(B_ * FHID + 255) / 256, 256>>>();
    // Layer 3 GEMM -> g_cur3 [n, 10]
    gemm3_kernel<<<NTOK / 256, 256>>>(W3, b3);
    // LIF3 -> out [b,o,t]
    lif3_kernel<<<(B_ * FOUT + 255) / 256, 256>>>(out);
}

// round 8
// speedup vs baseline: 1.3470x; 1.0468x over previous
#include <cuda_runtime.h>
#include <cuda_bf16.h>
#include <cstdint>

// Problem dims
#define B_    256
#define T_    100
#define FIN   784
#define FHID  500
#define FOUT  10
#define NTOK  25600   // B_*T_

// Neuron constants
#define EMF  0.7788007830714049f
#define A1F  1.1466802242428472f
#define A2F  -0.2865047968601901f

typedef __nv_bfloat16 bf16;

// ---------------------------------------------------------------------------
// Scratch (device globals; no allocation allowed)
// ---------------------------------------------------------------------------
__device__ float g_ann [NTOK * 1000];   // [n,1000] fp32
__device__ float g_cur2[NTOK * FHID];   // [n,500]
__device__ float g_psp3[NTOK * FHID];   // [n,500]
__device__ float g_cur3[NTOK * FOUT];   // [n,10]
// bf16x3 split operand planes (zero-padded to tile multiples)
__device__ bf16 g_w1p[3][1024 * 800];
__device__ bf16 g_w2p[3][512 * 512];
__device__ bf16 g_xp [3][NTOK * 800];
__device__ bf16 g_p2p[3][NTOK * 512];

// ---------------------------------------------------------------------------
// MMA helpers (baseline PTX, valid on plain sm_103 target)
// ---------------------------------------------------------------------------
__device__ __forceinline__ uint32_t smem_u32(const void* p) {
    uint32_t a;
    asm("{ .reg .u64 t; cvta.to.shared.u64 t, %1; cvt.u32.u64 %0, t; }"
        : "=r"(a) : "l"(p));
    return a;
}
__device__ __forceinline__ void ldsm4(uint32_t* r, uint32_t addr) {
    asm volatile("ldmatrix.sync.aligned.m8n8.x4.shared.b16 {%0,%1,%2,%3}, [%4];"
        : "=r"(r[0]), "=r"(r[1]), "=r"(r[2]), "=r"(r[3]) : "r"(addr));
}
__device__ __forceinline__ void ldsm2(uint32_t* r, uint32_t addr) {
    asm volatile("ldmatrix.sync.aligned.m8n8.x2.shared.b16 {%0,%1}, [%2];"
        : "=r"(r[0]), "=r"(r[1]) : "r"(addr));
}
__device__ __forceinline__ void mma_bf16(float* d, const uint32_t* a, const uint32_t* b) {
    asm volatile("mma.sync.aligned.m16n8k16.row.col.f32.bf16.bf16.f32 "
        "{%0,%1,%2,%3}, {%4,%5,%6,%7}, {%8,%9}, {%0,%1,%2,%3};"
        : "+f"(d[0]), "+f"(d[1]), "+f"(d[2]), "+f"(d[3])
        : "r"(a[0]), "r"(a[1]), "r"(a[2]), "r"(a[3]), "r"(b[0]), "r"(b[1]));
}
#define CP16(dst, src) \
    asm volatile("cp.async.cg.shared.global [%0], [%1], 16;" :: "r"(dst), "l"(src))
#define CP_COMMIT() asm volatile("cp.async.commit_group;" ::: "memory")
#define CP_WAIT0()  asm volatile("cp.async.wait_group 0;" ::: "memory")

// ---------------------------------------------------------------------------
// bf16x3 split: residual <= ~2^-25 |x|, full fp32 exponent range
// ---------------------------------------------------------------------------
__device__ __forceinline__ void split3(float x, bf16& b0, bf16& b1, bf16& b2) {
    b0 = __float2bfloat16_rn(x);
    float r1 = __fsub_rn(x, __bfloat162float(b0));
    b1 = __float2bfloat16_rn(r1);
    b2 = __float2bfloat16_rn(__fsub_rn(r1, __bfloat162float(b1)));
}

// ---------------------------------------------------------------------------
// Weight pre-split (+ zero padding)
// ---------------------------------------------------------------------------
template<int SEL>
__global__ __launch_bounds__(256)
void split_w_kernel(const float* __restrict__ W) {
    constexpr int O  = SEL ? FHID : 1000;
    constexpr int K  = SEL ? FHID : FIN;
    constexpr int OP = SEL ? 512  : 1024;
    constexpr int KP = SEL ? 512  : 800;
    int i = blockIdx.x * 256 + threadIdx.x;
    if (i >= OP * KP) return;
    int o = i / KP, k = i - o * KP;
    float v = (o < O && k < K) ? W[o * K + k] : 0.f;
    bf16 b0, b1, b2;
    split3(v, b0, b1, b2);
    if (SEL) { g_w2p[0][i] = b0; g_w2p[1][i] = b1; g_w2p[2][i] = b2; }
    else     { g_w1p[0][i] = b0; g_w1p[1][i] = b1; g_w1p[2][i] = b2; }
}

// ---------------------------------------------------------------------------
// Inputs [b,784,t] -> transpose + split3 -> g_xp planes [n, 800]
// ---------------------------------------------------------------------------
__global__ __launch_bounds__(256)
void transpose_split_inputs(const float* __restrict__ inp) {
    __shared__ float s[32][105];
    const int b  = blockIdx.y;
    const int k0 = blockIdx.x * 32;
    for (int i = threadIdx.x; i < 3200; i += 256) {
        int kk = i / 100, t = i - kk * 100;
        int k = k0 + kk;
        s[kk][t] = (k < FIN) ? inp[b * (FIN * T_) + k * T_ + t] : 0.f;
    }
    __syncthreads();
    for (int i = threadIdx.x; i < 3200; i += 256) {
        int t = i >> 5, kk = i & 31;
        bf16 b0, b1, b2;
        split3(s[kk][t], b0, b1, b2);
        int idx = (b * T_ + t) * 800 + k0 + kk;
        g_xp[0][idx] = b0;
        g_xp[1][idx] = b1;
        g_xp[2][idx] = b2;
    }
}

// ---------------------------------------------------------------------------
// GEMM on HMMA, bf16x3 split, CHUNKED RN ACCUMULATION:
//   main product (b0*b0) -> fresh per-chunk accumulator accC, folded into the
//   running total accT with IEEE-RN fp32 adds each chunk (kills TC RZ bias);
//   small products (01,10,11,02,20) -> separate small-magnitude accumulator.
// CTA 128(o) x 64(n), BK=32, 8 warps (warp tile 64x16).
// smem: A 2buf x 3pl x 128 x 80B = 61440; B 2 x 3 x 64 x 80B = 30720.
// ---------------------------------------------------------------------------
template<int SEL>  // 0: O=1000,KP=800, RELU, Y=g_ann; 1: O=500,KP=512, Y=g_cur2
__global__ __launch_bounds__(256)
void gemm_b3(const float* __restrict__ bias) {
    constexpr int O   = SEL ? FHID : 1000;
    constexpr int KP  = SEL ? 512  : 800;
    constexpr int NCH = KP / 32;
    const bf16* __restrict__ A0 = SEL ? g_w2p[0] : g_w1p[0];
    const bf16* __restrict__ A1 = SEL ? g_w2p[1] : g_w1p[1];
    const bf16* __restrict__ A2 = SEL ? g_w2p[2] : g_w1p[2];
    const bf16* __restrict__ B0 = SEL ? g_p2p[0] : g_xp[0];
    const bf16* __restrict__ B1 = SEL ? g_p2p[1] : g_xp[1];
    const bf16* __restrict__ B2 = SEL ? g_p2p[2] : g_xp[2];
    float* __restrict__ Y = SEL ? g_cur2 : g_ann;

    extern __shared__ __align__(16) char smem[];
    const uint32_t sbase = smem_u32(smem);
    const uint32_t sbB   = sbase + 61440;

    const int tid  = threadIdx.x;
    const int lane = tid & 31;
    const int wid  = tid >> 5;
    const int warp_o = wid >> 2;   // 0..1 (64 rows)
    const int warp_n = wid & 3;    // 0..3 (16 cols)
    const int o0 = blockIdx.x * 128;
    const int n0 = blockIdx.y * 64;

    // A loader: r = tid>>1 (0..127), kh = (tid&1)*16
    const int ra  = tid >> 1;
    const int kh  = (tid & 1) * 16;
    const uint32_t sts_a = sbase + ra * 80 + kh * 2;   // + buf*30720 + pl*10240
    const bf16* ga[3] = { A0 + (o0 + ra) * KP + kh, A1 + (o0 + ra) * KP + kh,
                          A2 + (o0 + ra) * KP + kh };
    // B loader: rb = tid>>2 (0..63), kq = (tid&3)*8
    const int rb = tid >> 2;
    const int kq = (tid & 3) * 8;
    const uint32_t sts_b = sbB + rb * 80 + kq * 2;     // + buf*15360 + pl*5120
    const bf16* gb[3] = { B0 + (n0 + rb) * KP + kq, B1 + (n0 + rb) * KP + kq,
                          B2 + (n0 + rb) * KP + kq };

    float accT[4][2][4];   // running total (RN-folded)
    float accS[4][2][4];   // running small-product accumulator (tiny magnitude)
    #pragma unroll
    for (int mt = 0; mt < 4; mt++)
        #pragma unroll
        for (int nt = 0; nt < 2; nt++)
            #pragma unroll
            for (int i = 0; i < 4; i++) { accT[mt][nt][i] = 0.f; accS[mt][nt][i] = 0.f; }

    auto load_chunk = [&](int c, int buf) {
        const int ko = c * 32;
        #pragma unroll
        for (int pl = 0; pl < 3; pl++) {
            const uint32_t da = sts_a + buf * 30720 + pl * 10240;
            CP16(da,      ga[pl] + ko);
            CP16(da + 16, ga[pl] + ko + 8);
            const uint32_t db = sts_b + buf * 15360 + pl * 5120;
            CP16(db, gb[pl] + ko);
        }
    };

    // ldmatrix lane addressing (80B pitch is conflict-free for 8-row LDSM)
    const uint32_t a_lane = (uint32_t)((lane & 15) * 80 + (lane >> 4) * 16);
    const int lb = lane & 15;
    const uint32_t b_lane = (uint32_t)((lb & 7) * 80 + (lb >> 3) * 16);
    const uint32_t abase0 = sbase + warp_o * 5120 + a_lane;   // 64 rows * 80B
    const uint32_t bbase0 = sbB + warp_n * 1280 + b_lane;     // 16 rows * 80B

    load_chunk(0, 0);
    CP_COMMIT();
    CP_WAIT0();
    __syncthreads();

    for (int c = 0; c < NCH; c++) {
        const int buf = c & 1;
        if (c + 1 < NCH) { load_chunk(c + 1, buf ^ 1); CP_COMMIT(); }

        float accC[4][2][4];   // fresh per-chunk accumulator for main product
        #pragma unroll
        for (int mt = 0; mt < 4; mt++)
            #pragma unroll
            for (int nt = 0; nt < 2; nt++)
                #pragma unroll
                for (int i = 0; i < 4; i++) accC[mt][nt][i] = 0.f;

        #pragma unroll
        for (int ks = 0; ks < 2; ks++) {
            uint32_t af[3][4][4];
            const uint32_t ab = abase0 + buf * 30720 + ks * 32;
            #pragma unroll
            for (int p = 0; p < 3; p++)
                #pragma unroll
                for (int mt = 0; mt < 4; mt++)
                    ldsm4(af[p][mt], ab + p * 10240 + mt * 1280);
            uint32_t bfr[3][2][2];
            const uint32_t bb = bbase0 + buf * 15360 + ks * 32;
            #pragma unroll
            for (int p = 0; p < 3; p++)
                #pragma unroll
                for (int nt = 0; nt < 2; nt++)
                    ldsm2(bfr[p][nt], bb + p * 5120 + nt * 640);

            // main product b0*b0 -> accC (fresh this chunk)
            #pragma unroll
            for (int mt = 0; mt < 4; mt++)
                #pragma unroll
                for (int nt = 0; nt < 2; nt++)
                    mma_bf16(accC[mt][nt], af[0][mt], bfr[0][nt]);

            // small products -> accS (running; magnitude ~2^-9 of main)
            const int PA[5] = {0, 1, 1, 0, 2};
            const int PB[5] = {1, 0, 1, 2, 0};
            #pragma unroll
            for (int p = 0; p < 5; p++)
                #pragma unroll
                for (int mt = 0; mt < 4; mt++)
                    #pragma unroll
                    for (int nt = 0; nt < 2; nt++)
                        mma_bf16(accS[mt][nt], af[PA[p]][mt], bfr[PB[p]][nt]);
        }

        // fold chunk main into running total with IEEE-RN adds
        #pragma unroll
        for (int mt = 0; mt < 4; mt++)
            #pragma unroll
            for (int nt = 0; nt < 2; nt++)
                #pragma unroll
                for (int i = 0; i < 4; i++)
                    accT[mt][nt][i] = __fadd_rn(accT[mt][nt][i], accC[mt][nt][i]);

        if (c + 1 < NCH) CP_WAIT0();
        __syncthreads();
    }

    // total = accT + accS (RN)
    #pragma unroll
    for (int mt = 0; mt < 4; mt++)
        #pragma unroll
        for (int nt = 0; nt < 2; nt++)
            #pragma unroll
            for (int i = 0; i < 4; i++)
                accT[mt][nt][i] = __fadd_rn(accT[mt][nt][i], accS[mt][nt][i]);

    // ---- epilogue: transpose through smem, coalesced fp32 writes ----
    float* es = reinterpret_cast<float*>(smem);   // [64][132]
    #pragma unroll
    for (int mt = 0; mt < 4; mt++)
        #pragma unroll
        for (int nt = 0; nt < 2; nt++)
            #pragma unroll
            for (int i = 0; i < 4; i++) {
                int ol = warp_o * 64 + mt * 16 + (lane >> 2) + 8 * (i >> 1);
                int nl = warp_n * 16 + nt * 8 + 2 * (lane & 3) + (i & 1);
                es[nl * 132 + ol] = accT[mt][nt][i];
            }
    __syncthreads();
    for (int it = tid; it < 64 * 32; it += 256) {
        int nl = it >> 5;
        int c4 = (it & 31) * 4;
        int o  = o0 + c4;
        if (o < O) {
            float4 v  = *reinterpret_cast<const float4*>(&es[nl * 132 + c4]);
            float4 bv = *reinterpret_cast<const float4*>(&bias[o]);
            v.x = __fadd_rn(v.x, bv.x);
            v.y = __fadd_rn(v.y, bv.y);
            v.z = __fadd_rn(v.z, bv.z);
            v.w = __fadd_rn(v.w, bv.w);
            if (!SEL) {
                v.x = fmaxf(v.x, 0.f); v.y = fmaxf(v.y, 0.f);
                v.z = fmaxf(v.z, 0.f); v.w = fmaxf(v.w, 0.f);
            }
            *reinterpret_cast<float4*>(&Y[(n0 + nl) * O + o]) = v;
        }
    }
}

// ---------------------------------------------------------------------------
// Threefry2x32-20, key=(0,42); partitionable path (verified bit-exact)
// ---------------------------------------------------------------------------
__device__ __forceinline__ unsigned rotl32(unsigned x, int r) {
    return (x << r) | (x >> (32 - r));
}
__device__ __forceinline__ void threefry2x32_k42(unsigned c0, unsigned c1,
                                                 unsigned& o0, unsigned& o1) {
    const unsigned k0 = 0u, k1 = 42u;
    const unsigned k2 = 0x1BD11BDAu ^ k0 ^ k1;
    unsigned x0 = c0 + k0;
    unsigned x1 = c1 + k1;
#define TFR(r) { x0 += x1; x1 = rotl32(x1, (r)); x1 ^= x0; }
    TFR(13) TFR(15) TFR(26) TFR(6)
    x0 += k1; x1 += k2 + 1u;
    TFR(17) TFR(29) TFR(16) TFR(24)
    x0 += k2; x1 += k0 + 2u;
    TFR(13) TFR(15) TFR(26) TFR(6)
    x0 += k0; x1 += k1 + 3u;
    TFR(17) TFR(29) TFR(16) TFR(24)
    x0 += k1; x1 += k2 + 4u;
    TFR(13) TFR(15) TFR(26) TFR(6)
    x0 += k2; x1 += k0 + 5u;
#undef TFR
    o0 = x0; o1 = x1;
}
__device__ __forceinline__ float xla_erfinv32(float x) {
    float w = -log1pf(__fmul_rn(-x, x));
    float p;
    if (w < 5.0f) {
        w = __fadd_rn(w, -2.5f);
        p = 2.81022636e-08f;
        p = __fadd_rn(__fmul_rn(p, w),  3.43273939e-07f);
        p = __fadd_rn(__fmul_rn(p, w), -3.5233877e-06f);
        p = __fadd_rn(__fmul_rn(p, w), -4.39150654e-06f);
        p = __fadd_rn(__fmul_rn(p, w),  0.00021858087f);
        p = __fadd_rn(__fmul_rn(p, w), -0.00125372503f);
        p = __fadd_rn(__fmul_rn(p, w), -0.00417768164f);
        p = __fadd_rn(__fmul_rn(p, w),  0.246640727f);
        p = __fadd_rn(__fmul_rn(p, w),  1.50140941f);
    } else {
        w = __fadd_rn(sqrtf(w), -3.0f);
        p = -0.000200214257f;
        p = __fadd_rn(__fmul_rn(p, w),  0.000100950558f);
        p = __fadd_rn(__fmul_rn(p, w),  0.00134934322f);
        p = __fadd_rn(__fmul_rn(p, w), -0.00367342844f);
        p = __fadd_rn(__fmul_rn(p, w),  0.00573950773f);
        p = __fadd_rn(__fmul_rn(p, w), -0.0076224613f);
        p = __fadd_rn(__fmul_rn(p, w),  0.00943887047f);
        p = __fadd_rn(__fmul_rn(p, w),  1.00167406f);
        p = __fadd_rn(__fmul_rn(p, w),  2.83297682f);
    }
    return __fmul_rn(p, x);
}
__device__ __forceinline__ float jax_normal_eps(unsigned i) {
    unsigned r0, r1;
    threefry2x32_k42(0u, i, r0, r1);
    unsigned bits = r0 ^ r1;
    float f = __fadd_rn(__uint_as_float((bits >> 9) | 0x3f800000u), -1.0f);
    float u = fmaxf(-0.99999994f, __fadd_rn(__fmul_rn(f, 2.0f), -0.99999994f));
    return __fmul_rn(1.41421356237309515f, xla_erfinv32(u));
}

// ---------------------------------------------------------------------------
// coding = mu + eps * exp(0.5*ln_var); psp2 = dual-exp IIR; emit bf16x3 planes
// ---------------------------------------------------------------------------
__global__ __launch_bounds__(256)
void coding_psp2_kernel() {
    int idx = blockIdx.x * blockDim.x + threadIdx.x;   // b*500+f
    if (idx >= B_ * FHID) return;
    int b = idx / FHID;
    int f = idx - b * FHID;
    const float* mu = g_ann + b * (T_ * 1000) + f;      // +1000 per t
    const float* lv = mu + FHID;
    if (f < 12) {
        bf16 z = __float2bfloat16(0.f);
        for (int t = 0; t < T_; t++) {
            int zi = (b * T_ + t) * 512 + FHID + f;
            g_p2p[0][zi] = z; g_p2p[1][zi] = z; g_p2p[2][zi] = z;
        }
    }
    unsigned base = (unsigned)idx * 100u;
    float y1 = 0.f, y2 = 0.f;
    #pragma unroll 4
    for (int t = 0; t < T_; t++) {
        float eps = jax_normal_eps(base + (unsigned)t);
        float sc  = expf(__fmul_rn(0.5f, lv[t * 1000]));
        float cod = __fadd_rn(mu[t * 1000], __fmul_rn(eps, sc));
        float y   = __fadd_rn(__fadd_rn(__fmul_rn(A1F, y1), __fmul_rn(A2F, y2)), cod);
        bf16 b0, b1, b2;
        split3(y, b0, b1, b2);
        int oi = (b * T_ + t) * 512 + f;
        g_p2p[0][oi] = b0;
        g_p2p[1][oi] = b1;
        g_p2p[2][oi] = b2;
        y2 = y1; y1 = y;
    }
}

// ---------------------------------------------------------------------------
// LIF2 + IIR -> g_psp3 [n,500]
// ---------------------------------------------------------------------------
__global__ __launch_bounds__(256)
void lif2_psp3_kernel() {
    int idx = blockIdx.x * blockDim.x + threadIdx.x;
    if (idx >= B_ * FHID) return;
    int b = idx / FHID;
    int f = idx - b * FHID;
    const float* c = g_cur2 + b * (T_ * FHID) + f;
    float* out     = g_psp3 + b * (T_ * FHID) + f;
    float v = 0.f, s = 0.f, y1 = 0.f, y2 = 0.f;
    #pragma unroll 4
    for (int t = 0; t < T_; t++) {
        float vn = __fadd_rn(__fmul_rn(__fmul_rn(v, EMF), __fsub_rn(1.0f, s)), c[t * FHID]);
        float spk = (vn > 1.0f) ? 1.0f : 0.0f;
        v = vn; s = spk;
        float y = __fadd_rn(__fadd_rn(__fmul_rn(A1F, y1), __fmul_rn(A2F, y2)), spk);
        out[t * FHID] = y;
        y2 = y1; y1 = y;
    }
}

// ---------------------------------------------------------------------------
// GEMM3 (fp32, tiny): cur3[n,o] = sum_k W3[o,k]*psp3[n,k] + b3[o]
// ---------------------------------------------------------------------------
__global__ __launch_bounds__(256)
void gemm3_kernel(const float* __restrict__ W3, const float* __restrict__ b3) {
    __shared__ __align__(16) float Ws[FOUT * FHID];
    for (int i = threadIdx.x; i < FOUT * FHID; i += 256) Ws[i] = W3[i];
    __syncthreads();
    int n = blockIdx.x * 256 + threadIdx.x;
    float acc[FOUT];
    #pragma unroll
    for (int o = 0; o < FOUT; o++) acc[o] = 0.f;
    const float4* xp = reinterpret_cast<const float4*>(g_psp3 + n * FHID);
    #pragma unroll 5
    for (int k4 = 0; k4 < FHID / 4; k4++) {
        float4 x = xp[k4];
        #pragma unroll
        for (int o = 0; o < FOUT; o++) {
            float4 w = *reinterpret_cast<const float4*>(&Ws[o * FHID + k4 * 4]);
            acc[o] += w.x * x.x;
            acc[o] += w.y * x.y;
            acc[o] += w.z * x.z;
            acc[o] += w.w * x.w;
        }
    }
    #pragma unroll
    for (int o = 0; o < FOUT; o++)
        g_cur3[n * FOUT + o] = __fadd_rn(acc[o], b3[o]);
}

// ---------------------------------------------------------------------------
// LIF3 -> output spikes [b,o,t]
// ---------------------------------------------------------------------------
__global__ __launch_bounds__(256)
void lif3_kernel(float* __restrict__ out) {
    int idx = blockIdx.x * blockDim.x + threadIdx.x;
    if (idx >= B_ * FOUT) return;
    int b = idx / FOUT;
    int o = idx - b * FOUT;
    const float* c = g_cur3 + b * (T_ * FOUT) + o;
    float* op = out + idx * T_;
    float v = 0.f, s = 0.f;
    #pragma unroll 4
    for (int t = 0; t < T_; t++) {
        float vn = __fadd_rn(__fmul_rn(__fmul_rn(v, EMF), __fsub_rn(1.0f, s)), c[t * FOUT]);
        float spk = (vn > 1.0f) ? 1.0f : 0.0f;
        v = vn; s = spk;
        op[t] = spk;
    }
}

// ---------------------------------------------------------------------------
extern "C" void kernel_launch(void* const* d_in, const int* in_sizes, int n_in,
                              void* d_out, int out_size) {
    const float* inputs = (const float*)d_in[0];
    const float* W1     = (const float*)d_in[1];
    const float* b1     = (const float*)d_in[2];
    const float* W2     = (const float*)d_in[3];
    const float* b2     = (const float*)d_in[4];
    const float* W3     = (const float*)d_in[5];
    const float* b3     = (const float*)d_in[6];
    float* out          = (float*)d_out;

    constexpr int GEMM_SMEM = 92160;
    cudaFuncSetAttribute(gemm_b3<0>, cudaFuncAttributeMaxDynamicSharedMemorySize, GEMM_SMEM);
    cudaFuncSetAttribute(gemm_b3<1>, cudaFuncAttributeMaxDynamicSharedMemorySize, GEMM_SMEM);

    // Prep: split weights + transpose/split inputs
    split_w_kernel<0><<<(1024 * 800 + 255) / 256, 256>>>(W1);
    split_w_kernel<1><<<(512 * 512 + 255) / 256, 256>>>(W2);
    transpose_split_inputs<<<dim3(25, 256), 256>>>(inputs);

    // Layer 1: ann = relu(W1 @ x + b1)
    gemm_b3<0><<<dim3(8, 400), 256, GEMM_SMEM>>>(b1);
    // coding + IIR -> bf16x3 planes
    coding_psp2_kernel<<<(B_ * FHID + 255) / 256, 256>>>();
    // Layer 2 GEMM
    gemm_b3<1><<<dim3(4, 400), 256, GEMM_SMEM>>>(b2);
    // LIF2 + IIR
    lif2_psp3_kernel<<<(B_ * FHID + 255) / 256, 256>>>();
    // Layer 3 GEMM + LIF
    gemm3_kernel<<<NTOK / 256, 256>>>(W3, b3);
    lif3_kernel<<<(B_ * FOUT + 255) / 256, 256>>>(out);
}

// round 10
// speedup vs baseline: 1.3962x; 1.0365x over previous
#include <cuda_runtime.h>
#include <cuda_bf16.h>
#include <cstdint>

// Problem dims
#define B_    256
#define T_    100
#define FIN   784
#define FHID  500
#define FOUT  10
#define NTOK  25600   // B_*T_

// Neuron constants
#define EMF  0.7788007830714049f
#define A1F  1.1466802242428472f
#define A2F  -0.2865047968601901f

typedef __nv_bfloat16 bf16;

// ---------------------------------------------------------------------------
// Scratch (device globals; no allocation allowed)
// ---------------------------------------------------------------------------
__device__ float g_ann [NTOK * 1000];   // [n,1000] fp32
__device__ float g_cur2[NTOK * FHID];   // [n,500]
__device__ float g_psp3[NTOK * FHID];   // [n,500]
__device__ float g_cur3[NTOK * FOUT];   // [n,10]
// bf16x3 split operand planes (zero-padded to tile multiples)
__device__ bf16 g_w1p[3][1024 * 800];
__device__ bf16 g_w2p[3][512 * 512];
__device__ bf16 g_xp [3][NTOK * 800];
__device__ bf16 g_p2p[3][NTOK * 512];

// ---------------------------------------------------------------------------
// MMA helpers (baseline PTX, valid on plain sm_103 target)
// ---------------------------------------------------------------------------
__device__ __forceinline__ uint32_t smem_u32(const void* p) {
    uint32_t a;
    asm("{ .reg .u64 t; cvta.to.shared.u64 t, %1; cvt.u32.u64 %0, t; }"
        : "=r"(a) : "l"(p));
    return a;
}
__device__ __forceinline__ void ldsm4(uint32_t* r, uint32_t addr) {
    asm volatile("ldmatrix.sync.aligned.m8n8.x4.shared.b16 {%0,%1,%2,%3}, [%4];"
        : "=r"(r[0]), "=r"(r[1]), "=r"(r[2]), "=r"(r[3]) : "r"(addr));
}
__device__ __forceinline__ void mma_bf16(float* d, const uint32_t* a, const uint32_t* b) {
    asm volatile("mma.sync.aligned.m16n8k16.row.col.f32.bf16.bf16.f32 "
        "{%0,%1,%2,%3}, {%4,%5,%6,%7}, {%8,%9}, {%0,%1,%2,%3};"
        : "+f"(d[0]), "+f"(d[1]), "+f"(d[2]), "+f"(d[3])
        : "r"(a[0]), "r"(a[1]), "r"(a[2]), "r"(a[3]), "r"(b[0]), "r"(b[1]));
}
#define CP16(dst, src) \
    asm volatile("cp.async.cg.shared.global [%0], [%1], 16;" :: "r"(dst), "l"(src))
#define CP_COMMIT() asm volatile("cp.async.commit_group;" ::: "memory")
#define CP_WAIT0()  asm volatile("cp.async.wait_group 0;" ::: "memory")

// ---------------------------------------------------------------------------
// bf16x3 split: residual <= ~2^-25 |x|, full fp32 exponent range
// ---------------------------------------------------------------------------
__device__ __forceinline__ void split3(float x, bf16& b0, bf16& b1, bf16& b2) {
    b0 = __float2bfloat16_rn(x);
    float r1 = __fsub_rn(x, __bfloat162float(b0));
    b1 = __float2bfloat16_rn(r1);
    b2 = __float2bfloat16_rn(__fsub_rn(r1, __bfloat162float(b1)));
}

// ---------------------------------------------------------------------------
// Weight pre-split (+ zero padding)
// ---------------------------------------------------------------------------
template<int SEL>
__global__ __launch_bounds__(256)
void split_w_kernel(const float* __restrict__ W) {
    constexpr int O  = SEL ? FHID : 1000;
    constexpr int K  = SEL ? FHID : FIN;
    constexpr int OP = SEL ? 512  : 1024;
    constexpr int KP = SEL ? 512  : 800;
    int i = blockIdx.x * 256 + threadIdx.x;
    if (i >= OP * KP) return;
    int o = i / KP, k = i - o * KP;
    float v = (o < O && k < K) ? W[o * K + k] : 0.f;
    bf16 b0, b1, b2;
    split3(v, b0, b1, b2);
    if (SEL) { g_w2p[0][i] = b0; g_w2p[1][i] = b1; g_w2p[2][i] = b2; }
    else     { g_w1p[0][i] = b0; g_w1p[1][i] = b1; g_w1p[2][i] = b2; }
}

// ---------------------------------------------------------------------------
// Inputs [b,784,t] -> transpose + split3 -> g_xp planes [n, 800]
// ---------------------------------------------------------------------------
__global__ __launch_bounds__(256)
void transpose_split_inputs(const float* __restrict__ inp) {
    __shared__ float s[32][105];
    const int b  = blockIdx.y;
    const int k0 = blockIdx.x * 32;
    for (int i = threadIdx.x; i < 3200; i += 256) {
        int kk = i / 100, t = i - kk * 100;
        int k = k0 + kk;
        s[kk][t] = (k < FIN) ? inp[b * (FIN * T_) + k * T_ + t] : 0.f;
    }
    __syncthreads();
    for (int i = threadIdx.x; i < 3200; i += 256) {
        int t = i >> 5, kk = i & 31;
        bf16 b0, b1, b2;
        split3(s[kk][t], b0, b1, b2);
        int idx = (b * T_ + t) * 800 + k0 + kk;
        g_xp[0][idx] = b0;
        g_xp[1][idx] = b1;
        g_xp[2][idx] = b2;
    }
}

// ---------------------------------------------------------------------------
// GEMM on HMMA, bf16x3 split, chunked RN accumulation (2 accumulator sets):
//   ALL 6 cross products of a chunk -> fresh accC, folded into accT with
//   IEEE-RN fp32 adds each 32-k chunk (kills TC RZ accumulation bias).
// CTA 128(o) x 64(n), BK=32, 8 warps (warp tile 64x16).
// smem: A 2buf x 3pl x 128 x 80B = 61440; B 2 x 3 x 64 x 80B = 30720.
// ---------------------------------------------------------------------------
template<int SEL>  // 0: O=1000,KP=800, RELU, Y=g_ann; 1: O=500,KP=512, Y=g_cur2
__global__ __launch_bounds__(256, 2)
void gemm_b3(const float* __restrict__ bias) {
    constexpr int O   = SEL ? FHID : 1000;
    constexpr int KP  = SEL ? 512  : 800;
    constexpr int NCH = KP / 32;
    const bf16* __restrict__ A0 = SEL ? g_w2p[0] : g_w1p[0];
    const bf16* __restrict__ A1 = SEL ? g_w2p[1] : g_w1p[1];
    const bf16* __restrict__ A2 = SEL ? g_w2p[2] : g_w1p[2];
    const bf16* __restrict__ B0 = SEL ? g_p2p[0] : g_xp[0];
    const bf16* __restrict__ B1 = SEL ? g_p2p[1] : g_xp[1];
    const bf16* __restrict__ B2 = SEL ? g_p2p[2] : g_xp[2];
    float* __restrict__ Y = SEL ? g_cur2 : g_ann;

    extern __shared__ __align__(16) char smem[];
    const uint32_t sbase = smem_u32(smem);
    const uint32_t sbB   = sbase + 61440;

    const int tid  = threadIdx.x;
    const int lane = tid & 31;
    const int wid  = tid >> 5;
    const int warp_o = wid >> 2;   // 0..1 (64 rows)
    const int warp_n = wid & 3;    // 0..3 (16 cols)
    const int o0 = blockIdx.x * 128;
    const int n0 = blockIdx.y * 64;

    // A loader: r = tid>>1 (0..127), kh = (tid&1)*16
    const int ra  = tid >> 1;
    const int kh  = (tid & 1) * 16;
    const uint32_t sts_a = sbase + ra * 80 + kh * 2;   // + buf*30720 + pl*10240
    const bf16* ga[3] = { A0 + (o0 + ra) * KP + kh, A1 + (o0 + ra) * KP + kh,
                          A2 + (o0 + ra) * KP + kh };
    // B loader: rb = tid>>2 (0..63), kq = (tid&3)*8
    const int rb = tid >> 2;
    const int kq = (tid & 3) * 8;
    const uint32_t sts_b = sbB + rb * 80 + kq * 2;     // + buf*15360 + pl*5120
    const bf16* gb[3] = { B0 + (n0 + rb) * KP + kq, B1 + (n0 + rb) * KP + kq,
                          B2 + (n0 + rb) * KP + kq };

    float accT[4][2][4];   // running total (RN-folded)
    #pragma unroll
    for (int mt = 0; mt < 4; mt++)
        #pragma unroll
        for (int nt = 0; nt < 2; nt++)
            #pragma unroll
            for (int i = 0; i < 4; i++) accT[mt][nt][i] = 0.f;

    auto load_chunk = [&](int c, int buf) {
        const int ko = c * 32;
        #pragma unroll
        for (int pl = 0; pl < 3; pl++) {
            const uint32_t da = sts_a + buf * 30720 + pl * 10240;
            CP16(da,      ga[pl] + ko);
            CP16(da + 16, ga[pl] + ko + 8);
            const uint32_t db = sts_b + buf * 15360 + pl * 5120;
            CP16(db, gb[pl] + ko);
        }
    };

    // ldmatrix lane addressing (80B pitch, conflict-free for 8-row groups)
    const uint32_t a_lane = (uint32_t)((lane & 15) * 80 + (lane >> 4) * 16);
    // B x4: lanes 0-7 -> n0-7/k0-7, 8-15 -> n0-7/k8-15, 16-23 -> n8-15/k0-7, 24-31 -> n8-15/k8-15
    const uint32_t b_lane = (uint32_t)((lane & 7) * 80 + ((lane >> 3) & 1) * 16 + (lane >> 4) * 640);
    const uint32_t abase0 = sbase + warp_o * 5120 + a_lane;   // 64 rows * 80B
    const uint32_t bbase0 = sbB + warp_n * 1280 + b_lane;     // 16 rows * 80B

    load_chunk(0, 0);
    CP_COMMIT();
    CP_WAIT0();
    __syncthreads();

    for (int c = 0; c < NCH; c++) {
        const int buf = c & 1;
        if (c + 1 < NCH) { load_chunk(c + 1, buf ^ 1); CP_COMMIT(); }

        float accC[4][2][4];   // fresh per-chunk accumulator (all 6 products)
        #pragma unroll
        for (int mt = 0; mt < 4; mt++)
            #pragma unroll
            for (int nt = 0; nt < 2; nt++)
                #pragma unroll
                for (int i = 0; i < 4; i++) accC[mt][nt][i] = 0.f;

        #pragma unroll
        for (int ks = 0; ks < 2; ks++) {
            // B fragments: one ldsm4 per plane covers both nt groups
            uint32_t bfr[3][4];
            const uint32_t bb = bbase0 + buf * 15360 + ks * 32;
            #pragma unroll
            for (int p = 0; p < 3; p++)
                ldsm4(bfr[p], bb + p * 5120);

            const uint32_t ab = abase0 + buf * 30720 + ks * 32;
            uint32_t af[4][4];
            // ---- A plane 0: products with B planes 0,1,2 ----
            #pragma unroll
            for (int mt = 0; mt < 4; mt++) ldsm4(af[mt], ab + mt * 1280);
            #pragma unroll
            for (int pb = 0; pb < 3; pb++)
                #pragma unroll
                for (int mt = 0; mt < 4; mt++)
                    #pragma unroll
                    for (int nt = 0; nt < 2; nt++)
                        mma_bf16(accC[mt][nt], af[mt], &bfr[pb][nt * 2]);
            // ---- A plane 1: products with B planes 0,1 ----
            #pragma unroll
            for (int mt = 0; mt < 4; mt++) ldsm4(af[mt], ab + 10240 + mt * 1280);
            #pragma unroll
            for (int pb = 0; pb < 2; pb++)
                #pragma unroll
                for (int mt = 0; mt < 4; mt++)
                    #pragma unroll
                    for (int nt = 0; nt < 2; nt++)
                        mma_bf16(accC[mt][nt], af[mt], &bfr[pb][nt * 2]);
            // ---- A plane 2: product with B plane 0 ----
            #pragma unroll
            for (int mt = 0; mt < 4; mt++) ldsm4(af[mt], ab + 20480 + mt * 1280);
            #pragma unroll
            for (int mt = 0; mt < 4; mt++)
                #pragma unroll
                for (int nt = 0; nt < 2; nt++)
                    mma_bf16(accC[mt][nt], af[mt], &bfr[0][nt * 2]);
        }

        // fold chunk into running total with IEEE-RN adds
        #pragma unroll
        for (int mt = 0; mt < 4; mt++)
            #pragma unroll
            for (int nt = 0; nt < 2; nt++)
                #pragma unroll
                for (int i = 0; i < 4; i++)
                    accT[mt][nt][i] = __fadd_rn(accT[mt][nt][i], accC[mt][nt][i]);

        if (c + 1 < NCH) CP_WAIT0();
        __syncthreads();
    }

    // ---- epilogue: transpose through smem, coalesced fp32 writes ----
    float* es = reinterpret_cast<float*>(smem);   // [64][132]
    #pragma unroll
    for (int mt = 0; mt < 4; mt++)
        #pragma unroll
        for (int nt = 0; nt < 2; nt++)
            #pragma unroll
            for (int i = 0; i < 4; i++) {
                int ol = warp_o * 64 + mt * 16 + (lane >> 2) + 8 * (i >> 1);
                int nl = warp_n * 16 + nt * 8 + 2 * (lane & 3) + (i & 1);
                es[nl * 132 + ol] = accT[mt][nt][i];
            }
    __syncthreads();
    for (int it = tid; it < 64 * 32; it += 256) {
        int nl = it >> 5;
        int c4 = (it & 31) * 4;
        int o  = o0 + c4;
        if (o < O) {
            float4 v  = *reinterpret_cast<const float4*>(&es[nl * 132 + c4]);
            float4 bv = *reinterpret_cast<const float4*>(&bias[o]);
            v.x = __fadd_rn(v.x, bv.x);
            v.y = __fadd_rn(v.y, bv.y);
            v.z = __fadd_rn(v.z, bv.z);
            v.w = __fadd_rn(v.w, bv.w);
            if (!SEL) {
                v.x = fmaxf(v.x, 0.f); v.y = fmaxf(v.y, 0.f);
                v.z = fmaxf(v.z, 0.f); v.w = fmaxf(v.w, 0.f);
            }
            *reinterpret_cast<float4*>(&Y[(n0 + nl) * O + o]) = v;
        }
    }
}

// ---------------------------------------------------------------------------
// Threefry2x32-20, key=(0,42); partitionable path (verified bit-exact)
// ---------------------------------------------------------------------------
__device__ __forceinline__ unsigned rotl32(unsigned x, int r) {
    return (x << r) | (x >> (32 - r));
}
__device__ __forceinline__ void threefry2x32_k42(unsigned c0, unsigned c1,
                                                 unsigned& o0, unsigned& o1) {
    const unsigned k0 = 0u, k1 = 42u;
    const unsigned k2 = 0x1BD11BDAu ^ k0 ^ k1;
    unsigned x0 = c0 + k0;
    unsigned x1 = c1 + k1;
#define TFR(r) { x0 += x1; x1 = rotl32(x1, (r)); x1 ^= x0; }
    TFR(13) TFR(15) TFR(26) TFR(6)
    x0 += k1; x1 += k2 + 1u;
    TFR(17) TFR(29) TFR(16) TFR(24)
    x0 += k2; x1 += k0 + 2u;
    TFR(13) TFR(15) TFR(26) TFR(6)
    x0 += k0; x1 += k1 + 3u;
    TFR(17) TFR(29) TFR(16) TFR(24)
    x0 += k1; x1 += k2 + 4u;
    TFR(13) TFR(15) TFR(26) TFR(6)
    x0 += k2; x1 += k0 + 5u;
#undef TFR
    o0 = x0; o1 = x1;
}
__device__ __forceinline__ float xla_erfinv32(float x) {
    float w = -log1pf(__fmul_rn(-x, x));
    float p;
    if (w < 5.0f) {
        w = __fadd_rn(w, -2.5f);
        p = 2.81022636e-08f;
        p = __fadd_rn(__fmul_rn(p, w),  3.43273939e-07f);
        p = __fadd_rn(__fmul_rn(p, w), -3.5233877e-06f);
        p = __fadd_rn(__fmul_rn(p, w), -4.39150654e-06f);
        p = __fadd_rn(__fmul_rn(p, w),  0.00021858087f);
        p = __fadd_rn(__fmul_rn(p, w), -0.00125372503f);
        p = __fadd_rn(__fmul_rn(p, w), -0.00417768164f);
        p = __fadd_rn(__fmul_rn(p, w),  0.246640727f);
        p = __fadd_rn(__fmul_rn(p, w),  1.50140941f);
    } else {
        w = __fadd_rn(sqrtf(w), -3.0f);
        p = -0.000200214257f;
        p = __fadd_rn(__fmul_rn(p, w),  0.000100950558f);
        p = __fadd_rn(__fmul_rn(p, w),  0.00134934322f);
        p = __fadd_rn(__fmul_rn(p, w), -0.00367342844f);
        p = __fadd_rn(__fmul_rn(p, w),  0.00573950773f);
        p = __fadd_rn(__fmul_rn(p, w), -0.0076224613f);
        p = __fadd_rn(__fmul_rn(p, w),  0.00943887047f);
        p = __fadd_rn(__fmul_rn(p, w),  1.00167406f);
        p = __fadd_rn(__fmul_rn(p, w),  2.83297682f);
    }
    return __fmul_rn(p, x);
}
__device__ __forceinline__ float jax_normal_eps(unsigned i) {
    unsigned r0, r1;
    threefry2x32_k42(0u, i, r0, r1);
    unsigned bits = r0 ^ r1;
    float f = __fadd_rn(__uint_as_float((bits >> 9) | 0x3f800000u), -1.0f);
    float u = fmaxf(-0.99999994f, __fadd_rn(__fmul_rn(f, 2.0f), -0.99999994f));
    return __fmul_rn(1.41421356237309515f, xla_erfinv32(u));
}

// ---------------------------------------------------------------------------
// coding = mu + eps * exp(0.5*ln_var); psp2 = dual-exp IIR; emit bf16x3 planes
// ---------------------------------------------------------------------------
__global__ __launch_bounds__(256)
void coding_psp2_kernel() {
    int idx = blockIdx.x * blockDim.x + threadIdx.x;   // b*500+f
    if (idx >= B_ * FHID) return;
    int b = idx / FHID;
    int f = idx - b * FHID;
    const float* mu = g_ann + b * (T_ * 1000) + f;      // +1000 per t
    const float* lv = mu + FHID;
    if (f < 12) {
        bf16 z = __float2bfloat16(0.f);
        for (int t = 0; t < T_; t++) {
            int zi = (b * T_ + t) * 512 + FHID + f;
            g_p2p[0][zi] = z; g_p2p[1][zi] = z; g_p2p[2][zi] = z;
        }
    }
    unsigned base = (unsigned)idx * 100u;
    float y1 = 0.f, y2 = 0.f;
    #pragma unroll 4
    for (int t = 0; t < T_; t++) {
        float eps = jax_normal_eps(base + (unsigned)t);
        float sc  = expf(__fmul_rn(0.5f, lv[t * 1000]));
        float cod = __fadd_rn(mu[t * 1000], __fmul_rn(eps, sc));
        float y   = __fadd_rn(__fadd_rn(__fmul_rn(A1F, y1), __fmul_rn(A2F, y2)), cod);
        bf16 b0, b1, b2;
        split3(y, b0, b1, b2);
        int oi = (b * T_ + t) * 512 + f;
        g_p2p[0][oi] = b0;
        g_p2p[1][oi] = b1;
        g_p2p[2][oi] = b2;
        y2 = y1; y1 = y;
    }
}

// ---------------------------------------------------------------------------
// LIF2 + IIR -> g_psp3 [n,500]
// ---------------------------------------------------------------------------
__global__ __launch_bounds__(256)
void lif2_psp3_kernel() {
    int idx = blockIdx.x * blockDim.x + threadIdx.x;
    if (idx >= B_ * FHID) return;
    int b = idx / FHID;
    int f = idx - b * FHID;
    const float* c = g_cur2 + b * (T_ * FHID) + f;
    float* out     = g_psp3 + b * (T_ * FHID) + f;
    float v = 0.f, s = 0.f, y1 = 0.f, y2 = 0.f;
    #pragma unroll 4
    for (int t = 0; t < T_; t++) {
        float vn = __fadd_rn(__fmul_rn(__fmul_rn(v, EMF), __fsub_rn(1.0f, s)), c[t * FHID]);
        float spk = (vn > 1.0f) ? 1.0f : 0.0f;
        v = vn; s = spk;
        float y = __fadd_rn(__fadd_rn(__fmul_rn(A1F, y1), __fmul_rn(A2F, y2)), spk);
        out[t * FHID] = y;
        y2 = y1; y1 = y;
    }
}

// ---------------------------------------------------------------------------
// GEMM3 (fp32, tiny): cur3[n,o] = sum_k W3[o,k]*psp3[n,k] + b3[o]
// ---------------------------------------------------------------------------
__global__ __launch_bounds__(256)
void gemm3_kernel(const float* __restrict__ W3, const float* __restrict__ b3) {
    __shared__ __align__(16) float Ws[FOUT * FHID];
    for (int i = threadIdx.x; i < FOUT * FHID; i += 256) Ws[i] = W3[i];
    __syncthreads();
    int n = blockIdx.x * 256 + threadIdx.x;
    float acc[FOUT];
    #pragma unroll
    for (int o = 0; o < FOUT; o++) acc[o] = 0.f;
    const float4* xp = reinterpret_cast<const float4*>(g_psp3 + n * FHID);
    #pragma unroll 5
    for (int k4 = 0; k4 < FHID / 4; k4++) {
        float4 x = xp[k4];
        #pragma unroll
        for (int o = 0; o < FOUT; o++) {
            float4 w = *reinterpret_cast<const float4*>(&Ws[o * FHID + k4 * 4]);
            acc[o] += w.x * x.x;
            acc[o] += w.y * x.y;
            acc[o] += w.z * x.z;
            acc[o] += w.w * x.w;
        }
    }
    #pragma unroll
    for (int o = 0; o < FOUT; o++)
        g_cur3[n * FOUT + o] = __fadd_rn(acc[o], b3[o]);
}

// ---------------------------------------------------------------------------
// LIF3 -> output spikes [b,o,t]
// ---------------------------------------------------------------------------
__global__ __launch_bounds__(256)
void lif3_kernel(float* __restrict__ out) {
    int idx = blockIdx.x * blockDim.x + threadIdx.x;
    if (idx >= B_ * FOUT) return;
    int b = idx / FOUT;
    int o = idx - b * FOUT;
    const float* c = g_cur3 + b * (T_ * FOUT) + o;
    float* op = out + idx * T_;
    float v = 0.f, s = 0.f;
    #pragma unroll 4
    for (int t = 0; t < T_; t++) {
        float vn = __fadd_rn(__fmul_rn(__fmul_rn(v, EMF), __fsub_rn(1.0f, s)), c[t * FOUT]);
        float spk = (vn > 1.0f) ? 1.0f : 0.0f;
        v = vn; s = spk;
        op[t] = spk;
    }
}

// ---------------------------------------------------------------------------
extern "C" void kernel_launch(void* const* d_in, const int* in_sizes, int n_in,
                              void* d_out, int out_size) {
    const float* inputs = (const float*)d_in[0];
    const float* W1     = (const float*)d_in[1];
    const float* b1     = (const float*)d_in[2];
    const float* W2     = (const float*)d_in[3];
    const float* b2     = (const float*)d_in[4];
    const float* W3     = (const float*)d_in[5];
    const float* b3     = (const float*)d_in[6];
    float* out          = (float*)d_out;

    constexpr int GEMM_SMEM = 92160;
    cudaFuncSetAttribute(gemm_b3<0>, cudaFuncAttributeMaxDynamicSharedMemorySize, GEMM_SMEM);
    cudaFuncSetAttribute(gemm_b3<1>, cudaFuncAttributeMaxDynamicSharedMemorySize, GEMM_SMEM);

    // Prep: split weights + transpose/split inputs
    split_w_kernel<0><<<(1024 * 800 + 255) / 256, 256>>>(W1);
    split_w_kernel<1><<<(512 * 512 + 255) / 256, 256>>>(W2);
    transpose_split_inputs<<<dim3(25, 256), 256>>>(inputs);

    // Layer 1: ann = relu(W1 @ x + b1)
    gemm_b3<0><<<dim3(8, 400), 256, GEMM_SMEM>>>(b1);
    // coding + IIR -> bf16x3 planes
    coding_psp2_kernel<<<(B_ * FHID + 255) / 256, 256>>>();
    // Layer 2 GEMM
    gemm_b3<1><<<dim3(4, 400), 256, GEMM_SMEM>>>(b2);
    // LIF2 + IIR
    lif2_psp3_kernel<<<(B_ * FHID + 255) / 256, 256>>>();
    // Layer 3 GEMM + LIF
    gemm3_kernel<<<NTOK / 256, 256>>>(W3, b3);
    lif3_kernel<<<(B_ * FOUT + 255) / 256, 256>>>(out);
}